// round 7
// baseline (speedup 1.0000x reference)
#include <cuda_runtime.h>
#include <cstdint>
#include <cstddef>

#define NN 20000
#define NE 640000
#define EPS 1e-8f

// B-operand tiled layout constants (words)
#define PWK 296                 // words per kp-row (16 kp per 32-k chunk)
#define GPW 36                  // words per g-row inside a kp-row
#define WCHUNK 4736             // words per 32-k weight chunk (16*296)

// ------------- device scratch (static, no allocations) -------------
__device__ float    g_aggr[NN * 128];
__device__ float    g_cacc[NN * 3];
__device__ uint32_t g_nft [NN * 128];
__device__ uint32_t g_eW1t[10 * WCHUNK];
__device__ uint32_t g_eW2t[4 * WCHUNK];
__device__ uint32_t g_nW1t[8 * WCHUNK];
__device__ uint32_t g_nW2t[4 * WCHUNK];
__device__ uint32_t g_cW1t[4 * WCHUNK];

// ------------- helpers -------------
__device__ __forceinline__ uint32_t f2tf(float x) {
    uint32_t u; asm("cvt.rna.tf32.f32 %0, %1;" : "=r"(u) : "f"(x)); return u;
}
__device__ __forceinline__ float silu(float x) { return x / (1.f + __expf(-x)); }

__device__ __forceinline__ void mma8(float* c, uint32_t a0, uint32_t a1, uint32_t a2, uint32_t a3,
                                     uint32_t b0, uint32_t b1) {
    asm volatile(
        "mma.sync.aligned.m16n8k8.row.col.f32.tf32.tf32.f32 "
        "{%0,%1,%2,%3},{%4,%5,%6,%7},{%8,%9},{%0,%1,%2,%3};"
        : "+f"(c[0]), "+f"(c[1]), "+f"(c[2]), "+f"(c[3])
        : "r"(a0), "r"(a1), "r"(a2), "r"(a3), "r"(b0), "r"(b1));
}
__device__ __forceinline__ void cpa(void* s, const void* g, bool v) {
    uint32_t sa = (uint32_t)__cvta_generic_to_shared(s);
    int sz = v ? 16 : 0;
    asm volatile("cp.async.cg.shared.global [%0],[%1],16,%2;" :: "r"(sa), "l"(g), "r"(sz));
}
__device__ __forceinline__ void cpcommit() { asm volatile("cp.async.commit_group;"); }
template <int N> __device__ __forceinline__ void cpwait() {
    asm volatile("cp.async.wait_group %0;" :: "n"(N));
}
__device__ __forceinline__ void redv4(float* gp, float x, float y, float z, float w) {
    asm volatile("red.global.add.v4.f32 [%0],{%1,%2,%3,%4};"
                 :: "l"(gp), "f"(x), "f"(y), "f"(z), "f"(w));
}

// weight permutation: element (k, c) of a K x 128-col (or 64-col) weight goes to
// chunk*WCHUNK + (t + 4s)*PWK + (c&7)*GPW + (c>>3)*2 + e, where k&31 = 8t + 2s + e.
// Reader (warp lane tig, step ks) then finds b0/b1 for all nt contiguous.
__device__ __forceinline__ int wperm(int k, int c) {
    int kk = k & 31;
    int t = kk >> 3, rem = kk & 7, s = rem >> 1, e = rem & 1;
    return (k >> 5) * WCHUNK + (t + 4 * s) * PWK + (c & 7) * GPW + ((c >> 3) << 1) + e;
}

// activation pitches (words): pitch = 4 mod 32 -> conflict-free LDS.128 A-frags
#define PX 36
#define PH 132

// ---- edge kernel smem layout (words) — X/H/M share one pool (disjoint lifetimes) ----
#define OFF_EB1 256
#define OFF_EB2 384
#define OFF_CB1 512
#define OFF_CW2 576
#define OFF_SCW 640
#define OFF_POOL 768                 // pool: 128*PH = 16896 words
#define OFF_X   OFF_POOL             // X double buffer (2*128*PX = 9216) inside pool
#define OFF_H   OFF_POOL
#define OFF_M   OFF_POOL
#define OFF_W   (OFF_POOL + 16896)   // W double buffer: 2*WCHUNK = 9472 words
#define EDGE_SMEM_WORDS (OFF_W + 2 * WCHUNK)       // 27136
#define EDGE_SMEM_BYTES (EDGE_SMEM_WORDS * 4)      // 108544

// ---- node kernel smem layout (words) ----
#define NOFF_B1 0
#define NOFF_B2 128
#define NOFF_POOL 256
#define NOFF_X  NOFF_POOL
#define NOFF_H  NOFF_POOL
#define NOFF_W  (NOFF_POOL + 16896)
#define NODE_SMEM_WORDS (NOFF_W + 2 * WCHUNK)      // 26624
#define NODE_SMEM_BYTES (NODE_SMEM_WORDS * 4)      // 106496

// ------------- GEMM chunk: one 32-wide K slab of a 128 x (NT*16) tile -------------
// warp layout: wm = warp&3 (rows wm*32..+31), wn = warp>>2 (N half)
// acc laid out as acc[(mt*NT + nt)*4 + q], mt in {0,1}
template <int NT, bool CVT>
__device__ __forceinline__ void chunk_mma(
    const uint32_t* __restrict__ A, int pa, int acol,
    const uint32_t* __restrict__ W,
    int wn, int wm, int g, int tig, float* acc)
{
    // A fragments for the whole chunk: 4 rows x 8 contiguous words (2 LDS.128 each)
    uint32_t a[4][8];
#pragma unroll
    for (int j = 0; j < 4; j++) {
        const uint32_t* p = A + (wm * 32 + j * 8 + g) * pa + acol + 8 * tig;
        uint4 v0 = *(const uint4*)p;
        uint4 v1 = *(const uint4*)(p + 4);
        a[j][0] = v0.x; a[j][1] = v0.y; a[j][2] = v0.z; a[j][3] = v0.w;
        a[j][4] = v1.x; a[j][5] = v1.y; a[j][6] = v1.z; a[j][7] = v1.w;
        if (CVT) {
#pragma unroll
            for (int w = 0; w < 8; w++) a[j][w] = f2tf(__uint_as_float(a[j][w]));
        }
    }
#pragma unroll
    for (int ks = 0; ks < 4; ks++) {
        // B fragments: NT*2 contiguous words -> NT/2 LDS.128
        const uint32_t* bp = W + (tig + 4 * ks) * PWK + g * GPW + wn * (NT * 2);
        uint32_t b[2 * NT];
#pragma unroll
        for (int v = 0; v < NT / 2; v++) {
            uint4 bv = *(const uint4*)(bp + v * 4);
            b[v * 4 + 0] = bv.x; b[v * 4 + 1] = bv.y; b[v * 4 + 2] = bv.z; b[v * 4 + 3] = bv.w;
        }
#pragma unroll
        for (int nt = 0; nt < NT; nt++) {
            uint32_t b0 = b[2 * nt], b1 = b[2 * nt + 1];
            mma8(acc + (0 * NT + nt) * 4,
                 a[0][2 * ks], a[1][2 * ks], a[0][2 * ks + 1], a[1][2 * ks + 1], b0, b1);
            mma8(acc + (1 * NT + nt) * 4,
                 a[2][2 * ks], a[3][2 * ks], a[2][2 * ks + 1], a[3][2 * ks + 1], b0, b1);
        }
    }
}

template <int N>
__device__ __forceinline__ void zero_acc(float* acc) {
#pragma unroll
    for (int q = 0; q < N; q++) acc[q] = 0.f;
}

// linear 16B memcpy of one pre-permuted weight chunk (WCHUNK words)
__device__ __forceinline__ void load_w_chunk(uint32_t* wb, const uint32_t* Wg, int kc, int tid) {
    const uint32_t* src = Wg + (size_t)kc * WCHUNK;
    for (int i = tid; i < WCHUNK / 4; i += 256)
        cpa(&wb[i * 4], &src[i * 4], true);
}

// ------------- prep: zero accumulators, pre-convert + pre-permute weights -------------
__global__ void prep_k(const float* __restrict__ nf, const float* __restrict__ eW1,
                       const float* __restrict__ eW2, const float* __restrict__ nW1,
                       const float* __restrict__ nW2, const float* __restrict__ cW1) {
    int i = blockIdx.x * 256 + threadIdx.x;
    int st = gridDim.x * 256;
    for (int j = i; j < NN * 128; j += st) { g_aggr[j] = 0.f; g_nft[j] = f2tf(nf[j]); }
    for (int j = i; j < NN * 3; j += st) g_cacc[j] = 0.f;
    for (int j = i; j < 320 * 128; j += st) g_eW1t[wperm(j >> 7, j & 127)] = f2tf(eW1[j]);
    for (int j = i; j < 128 * 128; j += st) {
        int d = wperm(j >> 7, j & 127);
        g_eW2t[d] = f2tf(eW2[j]);
        g_nW2t[d] = f2tf(nW2[j]);
    }
    for (int j = i; j < 256 * 128; j += st) g_nW1t[wperm(j >> 7, j & 127)] = f2tf(nW1[j]);
    for (int j = i; j < 128 * 64; j += st) g_cW1t[wperm(j >> 6, j & 63)] = f2tf(cW1[j]);
}

// ------------- edge kernel: fully fused edge MLP + scatter + coord head -------------
extern "C" __global__ void __launch_bounds__(256, 2)
edge_kernel(const int* __restrict__ ei, const float* __restrict__ ea,
            const float* __restrict__ coords,
            const float* __restrict__ eb1, const float* __restrict__ eb2,
            const float* __restrict__ cb1, const float* __restrict__ cw2,
            const float* __restrict__ cb2p)
{
    extern __shared__ uint32_t sm[];
    float* smf = (float*)sm;
    int* s_src = (int*)sm;
    int* s_dst = (int*)sm + 128;
    int tid = threadIdx.x;
    int e0 = blockIdx.x * 128;

    if (tid < 128) {
        s_src[tid] = ei[e0 + tid];
        s_dst[tid] = ei[NE + e0 + tid];
        smf[OFF_EB1 + tid] = eb1[tid];
        smf[OFF_EB2 + tid] = eb2[tid];
        smf[OFF_SCW + tid] = 0.f;
    }
    if (tid < 64) { smf[OFF_CB1 + tid] = cb1[tid]; smf[OFF_CW2 + tid] = cw2[tid]; }
    __syncthreads();

    int warp = tid >> 5, lane = tid & 31;
    int wm = warp & 3, wn = warp >> 2;
    int g = lane >> 2, tig = lane & 3;

    // X chunk loader: cols [0,128)=nf[src], [128,256)=nf[dst], [256,320)=edge_attr
    auto loadX = [&](int kc, int buf) {
        uint32_t* xb = sm + OFF_X + buf * (128 * PX);
#pragma unroll
        for (int q = 0; q < 4; q++) {
            int i = q * 256 + tid;
            int row = i >> 3, j = i & 7;
            const float* src;
            if (kc < 4)      src = (const float*)&g_nft[(size_t)s_src[row] * 128 + kc * 32 + j * 4];
            else if (kc < 8) src = (const float*)&g_nft[(size_t)s_dst[row] * 128 + (kc - 4) * 32 + j * 4];
            else             src = &ea[(size_t)(e0 + row) * 64 + (kc - 8) * 32 + j * 4];
            cpa(&xb[row * PX + j * 4], src, true);
        }
    };

    float acc[64];

    // ================= GEMM1: X[128,320] @ eW1 =================
    zero_acc<64>(acc);
    loadX(0, 0); load_w_chunk(sm + OFF_W, g_eW1t, 0, tid); cpcommit();
    for (int kc = 0; kc < 10; kc++) {
        int cur = kc & 1;
        if (kc < 9) {
            loadX(kc + 1, cur ^ 1);
            load_w_chunk(sm + OFF_W + (cur ^ 1) * WCHUNK, g_eW1t, kc + 1, tid);
            cpcommit(); cpwait<1>();
        } else cpwait<0>();
        __syncthreads();
        chunk_mma<8, false>(sm + OFF_X + cur * (128 * PX), PX, 0,
                            sm + OFF_W + cur * WCHUNK, wn, wm, g, tig, acc);
        __syncthreads();
    }
    // epilogue1: +eb1, silu, tf32 -> H (reuses X pool; X dead past this sync)
#pragma unroll
    for (int mt = 0; mt < 2; mt++)
#pragma unroll
        for (int nt = 0; nt < 8; nt++) {
            float* ac = acc + (mt * 8 + nt) * 4;
            int r = wm * 32 + mt * 16 + g;
            int c = wn * 64 + nt * 8 + tig * 2;
            float b0 = smf[OFF_EB1 + c], b1 = smf[OFF_EB1 + c + 1];
            sm[OFF_H + r * PH + c]           = f2tf(silu(ac[0] + b0));
            sm[OFF_H + r * PH + c + 1]       = f2tf(silu(ac[1] + b1));
            sm[OFF_H + (r + 8) * PH + c]     = f2tf(silu(ac[2] + b0));
            sm[OFF_H + (r + 8) * PH + c + 1] = f2tf(silu(ac[3] + b1));
        }
    __syncthreads();

    // ================= GEMM2: H[128,128] @ eW2 =================
    zero_acc<64>(acc);
    load_w_chunk(sm + OFF_W, g_eW2t, 0, tid); cpcommit();
    for (int kc = 0; kc < 4; kc++) {
        int cur = kc & 1;
        if (kc < 3) {
            load_w_chunk(sm + OFF_W + (cur ^ 1) * WCHUNK, g_eW2t, kc + 1, tid);
            cpcommit(); cpwait<1>();
        } else cpwait<0>();
        __syncthreads();
        chunk_mma<8, false>(sm + OFF_H, PH, kc * 32,
                            sm + OFF_W + cur * WCHUNK, wn, wm, g, tig, acc);
        __syncthreads();
    }
    // epilogue2: +eb2, silu -> MSG fp32 (overwrites H in place after sync)
#pragma unroll
    for (int mt = 0; mt < 2; mt++)
#pragma unroll
        for (int nt = 0; nt < 8; nt++) {
            float* ac = acc + (mt * 8 + nt) * 4;
            int r = wm * 32 + mt * 16 + g;
            int c = wn * 64 + nt * 8 + tig * 2;
            float b0 = smf[OFF_EB2 + c], b1 = smf[OFF_EB2 + c + 1];
            smf[OFF_M + r * PH + c]           = silu(ac[0] + b0);
            smf[OFF_M + r * PH + c + 1]       = silu(ac[1] + b1);
            smf[OFF_M + (r + 8) * PH + c]     = silu(ac[2] + b0);
            smf[OFF_M + (r + 8) * PH + c + 1] = silu(ac[3] + b1);
        }
    __syncthreads();

    // preload cW1 chunk 0 so its latency hides behind the scatter
    load_w_chunk(sm + OFF_W, g_cW1t, 0, tid); cpcommit();

    // scatter messages: 16B vector reductions into g_aggr (fire-and-forget)
    for (int i = tid; i < 4096; i += 256) {
        int row = i >> 5, j = (i & 31) * 4;
        const float* mp = &smf[OFF_M + row * PH + j];
        redv4(&g_aggr[(size_t)s_dst[row] * 128 + j], mp[0], mp[1], mp[2], mp[3]);
    }

    // ================= GEMM3: MSG[128,128] @ cW1[128,64] =================
    float acc3[32];
    zero_acc<32>(acc3);
    for (int kc = 0; kc < 4; kc++) {
        int cur = kc & 1;
        if (kc < 3) {
            load_w_chunk(sm + OFF_W + (cur ^ 1) * WCHUNK, g_cW1t, kc + 1, tid);
            cpcommit(); cpwait<1>();
        } else cpwait<0>();
        __syncthreads();
        chunk_mma<4, true>(sm + OFF_M, PH, kc * 32,
                           sm + OFF_W + cur * WCHUNK, wn, wm, g, tig, acc3);
        __syncthreads();
    }
    // coord-head epilogue: cw[row] = sum_c silu(T+cb1)*cW2
    {
        float pa0 = 0.f, pa1 = 0.f, pb0 = 0.f, pb1 = 0.f;
#pragma unroll
        for (int nt = 0; nt < 4; nt++) {
            float* a0 = acc3 + (0 * 4 + nt) * 4;
            float* a1 = acc3 + (1 * 4 + nt) * 4;
            int c = wn * 32 + nt * 8 + tig * 2;
            float b0 = smf[OFF_CB1 + c], b1 = smf[OFF_CB1 + c + 1];
            float w0 = smf[OFF_CW2 + c], w1 = smf[OFF_CW2 + c + 1];
            pa0 += silu(a0[0] + b0) * w0 + silu(a0[1] + b1) * w1;
            pa1 += silu(a0[2] + b0) * w0 + silu(a0[3] + b1) * w1;
            pb0 += silu(a1[0] + b0) * w0 + silu(a1[1] + b1) * w1;
            pb1 += silu(a1[2] + b0) * w0 + silu(a1[3] + b1) * w1;
        }
#pragma unroll
        for (int off = 1; off <= 2; off <<= 1) {
            pa0 += __shfl_xor_sync(0xffffffffu, pa0, off);
            pa1 += __shfl_xor_sync(0xffffffffu, pa1, off);
            pb0 += __shfl_xor_sync(0xffffffffu, pb0, off);
            pb1 += __shfl_xor_sync(0xffffffffu, pb1, off);
        }
        if (tig == 0) {
            atomicAdd(&smf[OFF_SCW + wm * 32 + g], pa0);
            atomicAdd(&smf[OFF_SCW + wm * 32 + g + 8], pa1);
            atomicAdd(&smf[OFF_SCW + wm * 32 + 16 + g], pb0);
            atomicAdd(&smf[OFF_SCW + wm * 32 + 16 + g + 8], pb1);
        }
    }
    __syncthreads();

    // coordinate update scatter
    if (tid < 128) {
        float cw = smf[OFF_SCW + tid] + __ldg(cb2p);
        int s = s_src[tid], d = s_dst[tid];
        float dx = __ldg(&coords[s * 3 + 0]) - __ldg(&coords[d * 3 + 0]);
        float dy = __ldg(&coords[s * 3 + 1]) - __ldg(&coords[d * 3 + 1]);
        float dz = __ldg(&coords[s * 3 + 2]) - __ldg(&coords[d * 3 + 2]);
        float sc = cw / (sqrtf(dx * dx + dy * dy + dz * dz) + EPS);
        atomicAdd(&g_cacc[d * 3 + 0], sc * dx);
        atomicAdd(&g_cacc[d * 3 + 1], sc * dy);
        atomicAdd(&g_cacc[d * 3 + 2], sc * dz);
    }
}

// ------------- node kernel: node MLP + residual + coords epilogue -------------
extern "C" __global__ void __launch_bounds__(256, 2)
node_kernel(const float* __restrict__ nf, const float* __restrict__ coords,
            const float* __restrict__ nb1, const float* __restrict__ nb2,
            float* __restrict__ out)
{
    extern __shared__ uint32_t sm[];
    float* smf = (float*)sm;
    int tid = threadIdx.x;
    int n0 = blockIdx.x * 128;

    if (tid < 128) { smf[NOFF_B1 + tid] = nb1[tid]; smf[NOFF_B2 + tid] = nb2[tid]; }
    __syncthreads();

    int warp = tid >> 5, lane = tid & 31;
    int wm = warp & 3, wn = warp >> 2;
    int g = lane >> 2, tig = lane & 3;

    auto loadX = [&](int kc, int buf) {
        uint32_t* xb = sm + NOFF_X + buf * (128 * PX);
#pragma unroll
        for (int q = 0; q < 4; q++) {
            int i = q * 256 + tid;
            int row = i >> 3, j = i & 7;
            int node = n0 + row;
            bool v = node < NN;
            const float* src;
            if (kc < 4) src = (const float*)&g_nft[v ? ((size_t)node * 128 + kc * 32 + j * 4) : 0];
            else        src = &g_aggr[v ? ((size_t)node * 128 + (kc - 4) * 32 + j * 4) : 0];
            cpa(&xb[row * PX + j * 4], src, v);
        }
    };

    float acc[64];

    // GEMM1: [nf | aggr][128,256] @ nW1
    zero_acc<64>(acc);
    loadX(0, 0); load_w_chunk(sm + NOFF_W, g_nW1t, 0, tid); cpcommit();
    for (int kc = 0; kc < 8; kc++) {
        int cur = kc & 1;
        if (kc < 7) {
            loadX(kc + 1, cur ^ 1);
            load_w_chunk(sm + NOFF_W + (cur ^ 1) * WCHUNK, g_nW1t, kc + 1, tid);
            cpcommit(); cpwait<1>();
        } else cpwait<0>();
        __syncthreads();
        chunk_mma<8, false>(sm + NOFF_X + cur * (128 * PX), PX, 0,
                            sm + NOFF_W + cur * WCHUNK, wn, wm, g, tig, acc);
        __syncthreads();
    }
#pragma unroll
    for (int mt = 0; mt < 2; mt++)
#pragma unroll
        for (int nt = 0; nt < 8; nt++) {
            float* ac = acc + (mt * 8 + nt) * 4;
            int r = wm * 32 + mt * 16 + g;
            int c = wn * 64 + nt * 8 + tig * 2;
            float b0 = smf[NOFF_B1 + c], b1 = smf[NOFF_B1 + c + 1];
            sm[NOFF_H + r * PH + c]           = f2tf(silu(ac[0] + b0));
            sm[NOFF_H + r * PH + c + 1]       = f2tf(silu(ac[1] + b1));
            sm[NOFF_H + (r + 8) * PH + c]     = f2tf(silu(ac[2] + b0));
            sm[NOFF_H + (r + 8) * PH + c + 1] = f2tf(silu(ac[3] + b1));
        }
    __syncthreads();

    // GEMM2: H @ nW2
    zero_acc<64>(acc);
    load_w_chunk(sm + NOFF_W, g_nW2t, 0, tid); cpcommit();
    for (int kc = 0; kc < 4; kc++) {
        int cur = kc & 1;
        if (kc < 3) {
            load_w_chunk(sm + NOFF_W + (cur ^ 1) * WCHUNK, g_nW2t, kc + 1, tid);
            cpcommit(); cpwait<1>();
        } else cpwait<0>();
        __syncthreads();
        chunk_mma<8, false>(sm + NOFF_H, PH, kc * 32,
                            sm + NOFF_W + cur * WCHUNK, wn, wm, g, tig, acc);
        __syncthreads();
    }
    // epilogue: residual + bias -> out nodes
#pragma unroll
    for (int mt = 0; mt < 2; mt++)
#pragma unroll
        for (int nt = 0; nt < 8; nt++) {
            float* ac = acc + (mt * 8 + nt) * 4;
            int r = wm * 32 + mt * 16 + g;
            int c = wn * 64 + nt * 8 + tig * 2;
            float b0 = smf[NOFF_B2 + c], b1 = smf[NOFF_B2 + c + 1];
            int na = n0 + r, nb = n0 + r + 8;
            if (na < NN) {
                out[(size_t)na * 128 + c]     = ac[0] + b0 + __ldg(&nf[(size_t)na * 128 + c]);
                out[(size_t)na * 128 + c + 1] = ac[1] + b1 + __ldg(&nf[(size_t)na * 128 + c + 1]);
            }
            if (nb < NN) {
                out[(size_t)nb * 128 + c]     = ac[2] + b0 + __ldg(&nf[(size_t)nb * 128 + c]);
                out[(size_t)nb * 128 + c + 1] = ac[3] + b1 + __ldg(&nf[(size_t)nb * 128 + c + 1]);
            }
        }

    // coords epilogue
    for (int i = tid; i < 384; i += 256) {
        int node = n0 + i / 3, k = i % 3;
        if (node < NN)
            out[(size_t)NN * 128 + node * 3 + k] = coords[node * 3 + k] + g_cacc[node * 3 + k];
    }
}

// ------------- host entry -------------
extern "C" void kernel_launch(void* const* d_in, const int* in_sizes, int n_in,
                              void* d_out, int out_size) {
    const float* nf     = (const float*)d_in[0];
    const int*   ei     = (const int*)d_in[1];
    const float* ea     = (const float*)d_in[2];
    const float* coords = (const float*)d_in[3];
    const float* eW1 = (const float*)d_in[4];
    const float* eb1 = (const float*)d_in[5];
    const float* eW2 = (const float*)d_in[6];
    const float* eb2 = (const float*)d_in[7];
    const float* nW1 = (const float*)d_in[8];
    const float* nb1 = (const float*)d_in[9];
    const float* nW2 = (const float*)d_in[10];
    const float* nb2 = (const float*)d_in[11];
    const float* cW1 = (const float*)d_in[12];
    const float* cb1 = (const float*)d_in[13];
    const float* cW2 = (const float*)d_in[14];
    const float* cb2 = (const float*)d_in[15];
    float* out = (float*)d_out;

    cudaFuncSetAttribute(edge_kernel, cudaFuncAttributeMaxDynamicSharedMemorySize, EDGE_SMEM_BYTES);
    cudaFuncSetAttribute(node_kernel, cudaFuncAttributeMaxDynamicSharedMemorySize, NODE_SMEM_BYTES);

    prep_k<<<512, 256>>>(nf, eW1, eW2, nW1, nW2, cW1);
    edge_kernel<<<NE / 128, 256, EDGE_SMEM_BYTES>>>(ei, ea, coords, eb1, eb2, cb1, cW2, cb2);
    node_kernel<<<(NN + 127) / 128, 256, NODE_SMEM_BYTES>>>(nf, coords, nb1, nb2, out);
}

// round 9
// speedup vs baseline: 1.4403x; 1.4403x over previous
#include <cuda_runtime.h>
#include <cuda_fp16.h>
#include <cstdint>
#include <cstddef>

#define NN 20000
#define NE 640000
#define EPS 1e-8f

#define WCH  2304   // words per 32-k chunk of a 128-col weight (pre-permuted)
#define WCH3 1280   // words per 32-k chunk of a 64-col weight

// ------------- device scratch (static, no allocations) -------------
__device__ float  g_aggr[NN * 128];
__device__ float  g_cacc[NN * 3];
__device__ __half g_nfh [NN * 128];          // node_feat, half, per-chunk permuted
__device__ __half g_eW1h[10 * WCH * 2];
__device__ __half g_eW2h[4 * WCH * 2];
__device__ __half g_nW1h[8 * WCH * 2];
__device__ __half g_nW2h[4 * WCH * 2];
__device__ __half g_cW1h[4 * WCH3 * 2];

// ------------- helpers -------------
__device__ __forceinline__ float silu(float x) { return x / (1.f + __expf(-x)); }

__device__ __forceinline__ void mmaf16(float* c, uint32_t a0, uint32_t a1, uint32_t a2,
                                       uint32_t a3, uint32_t b0, uint32_t b1) {
    asm volatile(
        "mma.sync.aligned.m16n8k16.row.col.f32.f16.f16.f32 "
        "{%0,%1,%2,%3},{%4,%5,%6,%7},{%8,%9},{%0,%1,%2,%3};"
        : "+f"(c[0]), "+f"(c[1]), "+f"(c[2]), "+f"(c[3])
        : "r"(a0), "r"(a1), "r"(a2), "r"(a3), "r"(b0), "r"(b1));
}
__device__ __forceinline__ void cpa(void* s, const void* g, bool v) {
    uint32_t sa = (uint32_t)__cvta_generic_to_shared(s);
    int sz = v ? 16 : 0;
    asm volatile("cp.async.cg.shared.global [%0],[%1],16,%2;" :: "r"(sa), "l"(g), "r"(sz));
}
__device__ __forceinline__ void cpcommit() { asm volatile("cp.async.commit_group;"); }
template <int N> __device__ __forceinline__ void cpwait() {
    asm volatile("cp.async.wait_group %0;" :: "n"(N));
}
__device__ __forceinline__ void redv4(float* gp, float x, float y, float z, float w) {
    asm volatile("red.global.add.v4.f32 [%0],{%1,%2,%3,%4};"
                 :: "l"(gp), "f"(x), "f"(y), "f"(z), "f"(w));
}
__device__ __forceinline__ uint32_t packh2(float a, float b) {
    __half2 h; h.x = __float2half_rn(a); h.y = __float2half_rn(b);
    return *reinterpret_cast<uint32_t*>(&h);
}

// weight permutation (half index) for 128-col weights
__device__ __forceinline__ int wp128(int k, int c) {
    int kc = k >> 5, s = (k >> 4) & 1, kp = k & 15;
    int e = kp >> 3, t = (kp & 7) >> 1, h = kp & 1;
    int g = c & 7, nt = (c >> 3) & 7, wn = c >> 6;
    int w = kc * WCH + ((s * 8 + g) * 4 + t) * 36 + wn * 16 + nt * 2 + e;
    return w * 2 + h;
}
// 64-col weights
__device__ __forceinline__ int wp64(int k, int c) {
    int kc = k >> 5, s = (k >> 4) & 1, kp = k & 15;
    int e = kp >> 3, t = (kp & 7) >> 1, h = kp & 1;
    int g = c & 7, nt = (c >> 3) & 3, wn = c >> 5;
    int w = kc * WCH3 + ((s * 8 + g) * 4 + t) * 20 + wn * 8 + nt * 2 + e;
    return w * 2 + h;
}

// ---- edge kernel smem (words) ----
#define OFF_EB1 256
#define OFF_EB2 384
#define OFF_CB1 512
#define OFF_CW2 576
#define OFF_SCW 640
#define OFF_POOL 768                 // pool 17408 words: X db(2x5120) / H(4x2048) / M(128x136)
#define OFF_W   (OFF_POOL + 17408)   // W double buffer: 2*WCH
#define EDGE_SMEM_WORDS (OFF_W + 2 * WCH)          // 22784
#define EDGE_SMEM_BYTES (EDGE_SMEM_WORDS * 4)      // 91136

// ---- node kernel smem (words) ----
#define NOFF_B1 0
#define NOFF_B2 128
#define NPOOL   256                  // pool 10240 words: X db(2x5120) / H(4x2048)
#define NOFF_W  (NPOOL + 10240)
#define NODE_SMEM_WORDS (NOFF_W + 2 * WCH)         // 15104
#define NODE_SMEM_BYTES (NODE_SMEM_WORDS * 4)      // 60416

// ------------- inner mma loop over one 32-k chunk -------------
// va[j]: j0 = row (wm*32+g), j1 = +8, j2 = +16, j3 = +24; comps x,y,z,w = k words
// (s0 lo, s0 hi, s1 lo, s1 hi). acc layout: (mt*NT + nt)*4.
template <int NT>
__device__ __forceinline__ void bloop(const uint4 (&va)[4], const uint32_t* __restrict__ W,
                                      int wn, int g, int tig, float* acc) {
    const int BW = (NT == 8) ? 36 : 20, WOF = (NT == 8) ? 16 : 8;
#pragma unroll
    for (int s = 0; s < 2; s++) {
        const uint32_t* bp = W + ((s * 8 + g) * 4 + tig) * BW + wn * WOF;
        uint32_t x0 = s ? va[0].z : va[0].x, x1 = s ? va[1].z : va[1].x;
        uint32_t y0 = s ? va[0].w : va[0].y, y1 = s ? va[1].w : va[1].y;
        uint32_t x2 = s ? va[2].z : va[2].x, x3 = s ? va[3].z : va[3].x;
        uint32_t y2 = s ? va[2].w : va[2].y, y3 = s ? va[3].w : va[3].y;
#pragma unroll
        for (int q = 0; q < NT / 2; q++) {
            uint4 b = *(const uint4*)(bp + q * 4);
            mmaf16(acc + (q * 2 + 0) * 4,      x0, x1, y0, y1, b.x, b.y);
            mmaf16(acc + (q * 2 + 1) * 4,      x0, x1, y0, y1, b.z, b.w);
            mmaf16(acc + (NT + q * 2 + 0) * 4, x2, x3, y2, y3, b.x, b.y);
            mmaf16(acc + (NT + q * 2 + 1) * 4, x2, x3, y2, y3, b.z, b.w);
        }
    }
}

// A already half+permuted in smem tile (row pitch 16 words)
template <int NT>
__device__ __forceinline__ void chunk_h(const uint32_t* __restrict__ A,
                                        const uint32_t* __restrict__ W,
                                        int wn, int wm, int g, int tig, float* acc) {
    uint4 va[4];
#pragma unroll
    for (int j = 0; j < 4; j++) {
        int r = wm * 32 + ((j >> 1) << 4) + ((j & 1) << 3) + g;
        va[j] = *(const uint4*)(A + r * 16 + 4 * tig);
    }
    bloop<NT>(va, W, wn, g, tig, acc);
}

// A is fp32 in smem (row pitch pa words) -> convert to half in registers
template <int NT>
__device__ __forceinline__ void chunk_c(const float* __restrict__ A, int pa,
                                        const uint32_t* __restrict__ W,
                                        int wn, int wm, int g, int tig, float* acc) {
    uint4 va[4];
#pragma unroll
    for (int j = 0; j < 4; j++) {
        int r = wm * 32 + ((j >> 1) << 4) + ((j & 1) << 3) + g;
        const float* p = A + r * pa + 2 * tig;
        uint32_t w[4];
#pragma unroll
        for (int u = 0; u < 4; u++) {
            float2 f = *(const float2*)(p + u * 8);
            w[u] = packh2(f.x, f.y);
        }
        va[j].x = w[0]; va[j].y = w[1]; va[j].z = w[2]; va[j].w = w[3];
    }
    bloop<NT>(va, W, wn, g, tig, acc);
}

template <int N>
__device__ __forceinline__ void zero_acc(float* acc) {
#pragma unroll
    for (int q = 0; q < N; q++) acc[q] = 0.f;
}

__device__ __forceinline__ void load_w(uint32_t* wb, const __half* Wh, int kc, int wchunk, int tid) {
    const uint32_t* src = (const uint32_t*)Wh + (size_t)kc * wchunk;
    for (int i = tid; i < wchunk / 4; i += 256)
        cpa(&wb[i * 4], &src[i * 4], true);
}

// ------------- prep: zero accumulators, convert+permute weights and node_feat -------------
__global__ void prep_k(const float* __restrict__ nf, const float* __restrict__ eW1,
                       const float* __restrict__ eW2, const float* __restrict__ nW1,
                       const float* __restrict__ nW2, const float* __restrict__ cW1) {
    int i = blockIdx.x * 256 + threadIdx.x;
    int st = gridDim.x * 256;
    for (int j = i; j < NN * 128; j += st) {
        g_aggr[j] = 0.f;
        int node = j >> 7, kk = j & 127, cc = kk >> 5, w = (kk & 31) >> 1, h = kk & 1;
        int p = (w & 3) * 4 + (w >> 2);
        g_nfh[node * 128 + cc * 32 + p * 2 + h] = __float2half_rn(nf[j]);
    }
    for (int j = i; j < NN * 3; j += st) g_cacc[j] = 0.f;
    for (int j = i; j < 320 * 128; j += st)
        g_eW1h[wp128(j >> 7, j & 127)] = __float2half_rn(eW1[j]);
    for (int j = i; j < 128 * 128; j += st) {
        int d = wp128(j >> 7, j & 127);
        g_eW2h[d] = __float2half_rn(eW2[j]);
        g_nW2h[d] = __float2half_rn(nW2[j]);
    }
    for (int j = i; j < 256 * 128; j += st)
        g_nW1h[wp128(j >> 7, j & 127)] = __float2half_rn(nW1[j]);
    for (int j = i; j < 128 * 64; j += st)
        g_cW1h[wp64(j >> 6, j & 63)] = __float2half_rn(cW1[j]);
}

// ------------- edge kernel -------------
extern "C" __global__ void __launch_bounds__(256, 2)
edge_kernel(const int* __restrict__ ei, const float* __restrict__ ea,
            const float* __restrict__ coords,
            const float* __restrict__ eb1, const float* __restrict__ eb2,
            const float* __restrict__ cb1, const float* __restrict__ cw2,
            const float* __restrict__ cb2p)
{
    extern __shared__ uint32_t sm[];
    float* smf = (float*)sm;
    int* s_src = (int*)sm;
    int* s_dst = (int*)sm + 128;
    int tid = threadIdx.x;
    int e0 = blockIdx.x * 128;

    if (tid < 128) {
        s_src[tid] = ei[e0 + tid];
        s_dst[tid] = ei[NE + e0 + tid];
        smf[OFF_EB1 + tid] = eb1[tid];
        smf[OFF_EB2 + tid] = eb2[tid];
        smf[OFF_SCW + tid] = 0.f;
    }
    if (tid < 64) { smf[OFF_CB1 + tid] = cb1[tid]; smf[OFF_CW2 + tid] = cw2[tid]; }
    __syncthreads();

    int warp = tid >> 5, lane = tid & 31;
    int wm = warp & 3, wn = warp >> 2;
    int g = lane >> 2, tig = lane & 3;

    // X loader: kc 0-3 = nf[src] (half), 4-7 = nf[dst] (half), 8-9 = edge_attr (fp32)
    auto loadX = [&](int kc, int buf) {
        uint32_t* xb = sm + OFF_POOL + buf * 5120;
        if (kc < 8) {
            const uint32_t* base = (const uint32_t*)g_nfh;
            const int* idxa = (kc < 4) ? s_src : s_dst;
            int cc = kc & 3;
#pragma unroll
            for (int q = 0; q < 2; q++) {
                int i = q * 256 + tid;
                int row = i >> 2, j = i & 3;
                cpa(&xb[row * 16 + j * 4], base + (size_t)idxa[row] * 64 + cc * 16 + j * 4, true);
            }
        } else {
            int cc = kc - 8;
#pragma unroll
            for (int q = 0; q < 4; q++) {
                int i = q * 256 + tid;
                int row = i >> 3, j = i & 7;
                cpa(&xb[row * 40 + j * 4], &ea[(size_t)(e0 + row) * 64 + cc * 32 + j * 4], true);
            }
        }
    };

    float acc[64];

    // ================= GEMM1: X[128,320] @ eW1 =================
    zero_acc<64>(acc);
    loadX(0, 0); load_w(sm + OFF_W, g_eW1h, 0, WCH, tid); cpcommit();
    for (int kc = 0; kc < 10; kc++) {
        int cur = kc & 1;
        if (kc < 9) {
            loadX(kc + 1, cur ^ 1);
            load_w(sm + OFF_W + (cur ^ 1) * WCH, g_eW1h, kc + 1, WCH, tid);
            cpcommit(); cpwait<1>();
        } else cpwait<0>();
        __syncthreads();
        if (kc < 8)
            chunk_h<8>(sm + OFF_POOL + cur * 5120, sm + OFF_W + cur * WCH, wn, wm, g, tig, acc);
        else
            chunk_c<8>((const float*)(sm + OFF_POOL + cur * 5120), 40,
                       sm + OFF_W + cur * WCH, wn, wm, g, tig, acc);
        __syncthreads();
    }
    // epilogue1: +eb1, silu -> H (half, permuted; X dead)
#pragma unroll
    for (int mt = 0; mt < 2; mt++)
#pragma unroll
        for (int nt = 0; nt < 8; nt++) {
            float* ac = acc + (mt * 8 + nt) * 4;
            int r = wm * 32 + mt * 16 + g;
            int c = wn * 64 + nt * 8 + tig * 2;
            float b0 = smf[OFF_EB1 + c], b1 = smf[OFF_EB1 + c + 1];
            int cc = wn * 2 + (nt >> 2);
            int p = tig * 4 + (nt & 3);
            sm[OFF_POOL + cc * 2048 + r * 16 + p]       = packh2(silu(ac[0] + b0), silu(ac[1] + b1));
            sm[OFF_POOL + cc * 2048 + (r + 8) * 16 + p] = packh2(silu(ac[2] + b0), silu(ac[3] + b1));
        }
    __syncthreads();

    // ================= GEMM2: H[128,128] @ eW2 =================
    zero_acc<64>(acc);
    load_w(sm + OFF_W, g_eW2h, 0, WCH, tid); cpcommit();
    for (int kc = 0; kc < 4; kc++) {
        int cur = kc & 1;
        if (kc < 3) {
            load_w(sm + OFF_W + (cur ^ 1) * WCH, g_eW2h, kc + 1, WCH, tid);
            cpcommit(); cpwait<1>();
        } else cpwait<0>();
        __syncthreads();
        chunk_h<8>(sm + OFF_POOL + kc * 2048, sm + OFF_W + cur * WCH, wn, wm, g, tig, acc);
        __syncthreads();
    }
    // epilogue2: +eb2, silu -> M fp32 pitch 136 (overwrites H pool after sync)
#pragma unroll
    for (int mt = 0; mt < 2; mt++)
#pragma unroll
        for (int nt = 0; nt < 8; nt++) {
            float* ac = acc + (mt * 8 + nt) * 4;
            int r = wm * 32 + mt * 16 + g;
            int c = wn * 64 + nt * 8 + tig * 2;
            float b0 = smf[OFF_EB2 + c], b1 = smf[OFF_EB2 + c + 1];
            smf[OFF_POOL + r * 136 + c]           = silu(ac[0] + b0);
            smf[OFF_POOL + r * 136 + c + 1]       = silu(ac[1] + b1);
            smf[OFF_POOL + (r + 8) * 136 + c]     = silu(ac[2] + b0);
            smf[OFF_POOL + (r + 8) * 136 + c + 1] = silu(ac[3] + b1);
        }
    __syncthreads();

    // preload cW1 chunk 0 (hides behind the scatter)
    load_w(sm + OFF_W, g_cW1h, 0, WCH3, tid); cpcommit();

    // scatter messages: 16B vector reductions into g_aggr (fire-and-forget)
    for (int i = tid; i < 4096; i += 256) {
        int row = i >> 5, j = (i & 31) * 4;
        const float* mp = &smf[OFF_POOL + row * 136 + j];
        redv4(&g_aggr[(size_t)s_dst[row] * 128 + j], mp[0], mp[1], mp[2], mp[3]);
    }

    // ================= GEMM3: M[128,128] @ cW1[128,64] =================
    float acc3[32];
    zero_acc<32>(acc3);
    for (int kc = 0; kc < 4; kc++) {
        int cur = kc & 1;
        if (kc < 3) {
            load_w(sm + OFF_W + (cur ^ 1) * WCH, g_cW1h, kc + 1, WCH3, tid);
            cpcommit(); cpwait<1>();
        } else cpwait<0>();
        __syncthreads();
        chunk_c<4>((const float*)(sm + OFF_POOL) + kc * 32, 136,
                   sm + OFF_W + cur * WCH, wn, wm, g, tig, acc3);
        __syncthreads();
    }
    // coord-head epilogue
    {
        float pa0 = 0.f, pa1 = 0.f, pb0 = 0.f, pb1 = 0.f;
#pragma unroll
        for (int nt = 0; nt < 4; nt++) {
            float* a0 = acc3 + nt * 4;
            float* a1 = acc3 + (4 + nt) * 4;
            int c = wn * 32 + nt * 8 + tig * 2;
            float b0 = smf[OFF_CB1 + c], b1 = smf[OFF_CB1 + c + 1];
            float w0 = smf[OFF_CW2 + c], w1 = smf[OFF_CW2 + c + 1];
            pa0 += silu(a0[0] + b0) * w0 + silu(a0[1] + b1) * w1;
            pa1 += silu(a0[2] + b0) * w0 + silu(a0[3] + b1) * w1;
            pb0 += silu(a1[0] + b0) * w0 + silu(a1[1] + b1) * w1;
            pb1 += silu(a1[2] + b0) * w0 + silu(a1[3] + b1) * w1;
        }
#pragma unroll
        for (int off = 1; off <= 2; off <<= 1) {
            pa0 += __shfl_xor_sync(0xffffffffu, pa0, off);
            pa1 += __shfl_xor_sync(0xffffffffu, pa1, off);
            pb0 += __shfl_xor_sync(0xffffffffu, pb0, off);
            pb1 += __shfl_xor_sync(0xffffffffu, pb1, off);
        }
        if (tig == 0) {
            atomicAdd(&smf[OFF_SCW + wm * 32 + g], pa0);
            atomicAdd(&smf[OFF_SCW + wm * 32 + g + 8], pa1);
            atomicAdd(&smf[OFF_SCW + wm * 32 + 16 + g], pb0);
            atomicAdd(&smf[OFF_SCW + wm * 32 + 16 + g + 8], pb1);
        }
    }
    __syncthreads();

    // coordinate update scatter
    if (tid < 128) {
        float cw = smf[OFF_SCW + tid] + __ldg(cb2p);
        int s = s_src[tid], d = s_dst[tid];
        float dx = __ldg(&coords[s * 3 + 0]) - __ldg(&coords[d * 3 + 0]);
        float dy = __ldg(&coords[s * 3 + 1]) - __ldg(&coords[d * 3 + 1]);
        float dz = __ldg(&coords[s * 3 + 2]) - __ldg(&coords[d * 3 + 2]);
        float sc = cw / (sqrtf(dx * dx + dy * dy + dz * dz) + EPS);
        atomicAdd(&g_cacc[d * 3 + 0], sc * dx);
        atomicAdd(&g_cacc[d * 3 + 1], sc * dy);
        atomicAdd(&g_cacc[d * 3 + 2], sc * dz);
    }
}

// ------------- node kernel -------------
extern "C" __global__ void __launch_bounds__(256, 2)
node_kernel(const float* __restrict__ nf, const float* __restrict__ coords,
            const float* __restrict__ nb1, const float* __restrict__ nb2,
            float* __restrict__ out)
{
    extern __shared__ uint32_t sm[];
    float* smf = (float*)sm;
    int tid = threadIdx.x;
    int n0 = blockIdx.x * 128;

    if (tid < 128) { smf[NOFF_B1 + tid] = nb1[tid]; smf[NOFF_B2 + tid] = nb2[tid]; }
    __syncthreads();

    int warp = tid >> 5, lane = tid & 31;
    int wm = warp & 3, wn = warp >> 2;
    int g = lane >> 2, tig = lane & 3;

    // X loader: kc 0-3 = nf (half, permuted), 4-7 = aggr (fp32)
    auto loadX = [&](int kc, int buf) {
        uint32_t* xb = sm + NPOOL + buf * 5120;
        if (kc < 4) {
#pragma unroll
            for (int q = 0; q < 2; q++) {
                int i = q * 256 + tid;
                int row = i >> 2, j = i & 3;
                int node = n0 + row;
                bool v = node < NN;
                cpa(&xb[row * 16 + j * 4],
                    (const uint32_t*)g_nfh + (size_t)(v ? node : 0) * 64 + kc * 16 + j * 4, v);
            }
        } else {
#pragma unroll
            for (int q = 0; q < 4; q++) {
                int i = q * 256 + tid;
                int row = i >> 3, j = i & 7;
                int node = n0 + row;
                bool v = node < NN;
                cpa(&xb[row * 40 + j * 4],
                    &g_aggr[(size_t)(v ? node : 0) * 128 + (kc - 4) * 32 + j * 4], v);
            }
        }
    };

    float acc[64];

    // GEMM1: [nf | aggr][128,256] @ nW1
    zero_acc<64>(acc);
    loadX(0, 0); load_w(sm + NOFF_W, g_nW1h, 0, WCH, tid); cpcommit();
    for (int kc = 0; kc < 8; kc++) {
        int cur = kc & 1;
        if (kc < 7) {
            loadX(kc + 1, cur ^ 1);
            load_w(sm + NOFF_W + (cur ^ 1) * WCH, g_nW1h, kc + 1, WCH, tid);
            cpcommit(); cpwait<1>();
        } else cpwait<0>();
        __syncthreads();
        if (kc < 4)
            chunk_h<8>(sm + NPOOL + cur * 5120, sm + NOFF_W + cur * WCH, wn, wm, g, tig, acc);
        else
            chunk_c<8>((const float*)(sm + NPOOL + cur * 5120), 40,
                       sm + NOFF_W + cur * WCH, wn, wm, g, tig, acc);
        __syncthreads();
    }
#pragma unroll
    for (int mt = 0; mt < 2; mt++)
#pragma unroll
        for (int nt = 0; nt < 8; nt++) {
            float* ac = acc + (mt * 8 + nt) * 4;
            int r = wm * 32 + mt * 16 + g;
            int c = wn * 64 + nt * 8 + tig * 2;
            float b0 = smf[NOFF_B1 + c], b1 = smf[NOFF_B1 + c + 1];
            int cc = wn * 2 + (nt >> 2);
            int p = tig * 4 + (nt & 3);
            sm[NPOOL + cc * 2048 + r * 16 + p]       = packh2(silu(ac[0] + b0), silu(ac[1] + b1));
            sm[NPOOL + cc * 2048 + (r + 8) * 16 + p] = packh2(silu(ac[2] + b0), silu(ac[3] + b1));
        }
    __syncthreads();

    // GEMM2: H @ nW2
    zero_acc<64>(acc);
    load_w(sm + NOFF_W, g_nW2h, 0, WCH, tid); cpcommit();
    for (int kc = 0; kc < 4; kc++) {
        int cur = kc & 1;
        if (kc < 3) {
            load_w(sm + NOFF_W + (cur ^ 1) * WCH, g_nW2h, kc + 1, WCH, tid);
            cpcommit(); cpwait<1>();
        } else cpwait<0>();
        __syncthreads();
        chunk_h<8>(sm + NPOOL + kc * 2048, sm + NOFF_W + cur * WCH, wn, wm, g, tig, acc);
        __syncthreads();
    }
    // epilogue: residual + bias -> out nodes
#pragma unroll
    for (int mt = 0; mt < 2; mt++)
#pragma unroll
        for (int nt = 0; nt < 8; nt++) {
            float* ac = acc + (mt * 8 + nt) * 4;
            int r = wm * 32 + mt * 16 + g;
            int c = wn * 64 + nt * 8 + tig * 2;
            float b0 = smf[NOFF_B2 + c], b1 = smf[NOFF_B2 + c + 1];
            int na = n0 + r, nb = n0 + r + 8;
            if (na < NN) {
                out[(size_t)na * 128 + c]     = ac[0] + b0 + __ldg(&nf[(size_t)na * 128 + c]);
                out[(size_t)na * 128 + c + 1] = ac[1] + b1 + __ldg(&nf[(size_t)na * 128 + c + 1]);
            }
            if (nb < NN) {
                out[(size_t)nb * 128 + c]     = ac[2] + b0 + __ldg(&nf[(size_t)nb * 128 + c]);
                out[(size_t)nb * 128 + c + 1] = ac[3] + b1 + __ldg(&nf[(size_t)nb * 128 + c + 1]);
            }
        }

    // coords epilogue
    for (int i = tid; i < 384; i += 256) {
        int node = n0 + i / 3, k = i % 3;
        if (node < NN)
            out[(size_t)NN * 128 + node * 3 + k] = coords[node * 3 + k] + g_cacc[node * 3 + k];
    }
}

// ------------- host entry -------------
extern "C" void kernel_launch(void* const* d_in, const int* in_sizes, int n_in,
                              void* d_out, int out_size) {
    const float* nf     = (const float*)d_in[0];
    const int*   ei     = (const int*)d_in[1];
    const float* ea     = (const float*)d_in[2];
    const float* coords = (const float*)d_in[3];
    const float* eW1 = (const float*)d_in[4];
    const float* eb1 = (const float*)d_in[5];
    const float* eW2 = (const float*)d_in[6];
    const float* eb2 = (const float*)d_in[7];
    const float* nW1 = (const float*)d_in[8];
    const float* nb1 = (const float*)d_in[9];
    const float* nW2 = (const float*)d_in[10];
    const float* nb2 = (const float*)d_in[11];
    const float* cW1 = (const float*)d_in[12];
    const float* cb1 = (const float*)d_in[13];
    const float* cW2 = (const float*)d_in[14];
    const float* cb2 = (const float*)d_in[15];
    float* out = (float*)d_out;

    cudaFuncSetAttribute(edge_kernel, cudaFuncAttributeMaxDynamicSharedMemorySize, EDGE_SMEM_BYTES);
    cudaFuncSetAttribute(node_kernel, cudaFuncAttributeMaxDynamicSharedMemorySize, NODE_SMEM_BYTES);

    prep_k<<<512, 256>>>(nf, eW1, eW2, nW1, nW2, cW1);
    edge_kernel<<<NE / 128, 256, EDGE_SMEM_BYTES>>>(ei, ea, coords, eb1, eb2, cb1, cW2, cb2);
    node_kernel<<<(NN + 127) / 128, 256, NODE_SMEM_BYTES>>>(nf, coords, nb1, nb2, out);
}